// round 1
// baseline (speedup 1.0000x reference)
#include <cuda_runtime.h>

#define NWIN 64
#define HD   32
#define NH   6
#define ATT_SCALE 0.17677669529663687f  // 32^-0.5

__device__ float g_bias[NH * NWIN * NWIN];

static __device__ __forceinline__ unsigned long long fma2(unsigned long long a,
                                                          unsigned long long b,
                                                          unsigned long long c) {
    unsigned long long d;
    asm("fma.rn.f32x2 %0, %1, %2, %3;" : "=l"(d) : "l"(a), "l"(b), "l"(c));
    return d;
}
static __device__ __forceinline__ unsigned long long pack2(float x, float y) {
    unsigned long long d;
    asm("mov.b64 %0, {%1, %2};" : "=l"(d) : "f"(x), "f"(y));
    return d;
}
static __device__ __forceinline__ float2 unpack2(unsigned long long u) {
    float2 r;
    asm("mov.b64 {%0, %1}, %2;" : "=f"(r.x), "=f"(r.y) : "l"(u));
    return r;
}

// ---------------------------------------------------------------------------
// Kernel 1: relative-position bias MLP  [64,64,2] -> [6,64,64]
// ---------------------------------------------------------------------------
__global__ void __launch_bounds__(256)
bias_kernel(const float* __restrict__ rel, const float* __restrict__ w1,
            const float* __restrict__ b1, const float* __restrict__ w2,
            const float* __restrict__ b2) {
    __shared__ float s_w1a[256];
    __shared__ float s_w1b[256];
    __shared__ float s_b1[256];
    __shared__ float s_w2[256 * NH];

    const int tid = threadIdx.x;
    s_w1a[tid] = w1[tid];
    s_w1b[tid] = w1[256 + tid];
    s_b1[tid]  = b1[tid];
#pragma unroll
    for (int i = tid; i < 256 * NH; i += 256) s_w2[i] = w2[i];
    __syncthreads();

    const int idx = blockIdx.x * 256 + tid;  // 0..4095 = i*64+j
    const float r0 = rel[idx * 2 + 0];
    const float r1 = rel[idx * 2 + 1];

    float acc[NH];
#pragma unroll
    for (int o = 0; o < NH; o++) acc[o] = 0.0f;

#pragma unroll 4
    for (int hh = 0; hh < 256; hh++) {
        float a = fmaf(r0, s_w1a[hh], fmaf(r1, s_w1b[hh], s_b1[hh]));
        a = fmaxf(a, 0.0f);
#pragma unroll
        for (int o = 0; o < NH; o++) acc[o] = fmaf(a, s_w2[hh * NH + o], acc[o]);
    }
#pragma unroll
    for (int o = 0; o < NH; o++) g_bias[o * 4096 + idx] = acc[o] + b2[o];
}

// ---------------------------------------------------------------------------
// Kernel 2: windowed attention. One CTA per (head, window). 256 threads.
//   smem strides: q/k = 34 (8B-aligned rows, conflict-free LDS.64 over d-pairs)
//                 v   = 36 (16B-aligned rows, conflict-free LDS.128)
//                 P   = 66
// ---------------------------------------------------------------------------
#define QK_STRIDE 34
#define V_STRIDE  36
#define P_STRIDE  66

__global__ void __launch_bounds__(256, 3)
attn_kernel(const float* __restrict__ qkv, float* __restrict__ out) {
    __shared__ float sq[NWIN * QK_STRIDE];
    __shared__ float sk[NWIN * QK_STRIDE];
    __shared__ float sv[NWIN * V_STRIDE];
    __shared__ float sp[NWIN * P_STRIDE];
    __shared__ float sinv[NWIN];

    const int tid = threadIdx.x;
    const int h = blockIdx.x;
    const int b = blockIdx.y;

    // ---- load q,k,v (64 x 32 each) -------------------------------------
    const float* base = qkv + (size_t)b * (NWIN * 576) + h * HD;
#pragma unroll
    for (int rep = 0; rep < 2; rep++) {
        const int it = tid + rep * 256;        // 0..511 float4 slots
        const int n = it >> 3;
        const int f = (it & 7) << 2;
        const float* g = base + n * 576 + f;
        float4 x = *(const float4*)(g);
        float4 y = *(const float4*)(g + 192);
        float4 z = *(const float4*)(g + 384);
        const int qo = n * QK_STRIDE + f;
        *(float2*)(sq + qo)     = make_float2(x.x, x.y);
        *(float2*)(sq + qo + 2) = make_float2(x.z, x.w);
        *(float2*)(sk + qo)     = make_float2(y.x, y.y);
        *(float2*)(sk + qo + 2) = make_float2(y.z, y.w);
        *(float4*)(sv + n * V_STRIDE + f) = z;
    }
    // ---- preload bias[h] into P buffer (overwritten by exp(P) later) ----
    const float* bp = g_bias + h * 4096;
#pragma unroll
    for (int rep = 0; rep < 4; rep++) {
        const int it = tid + rep * 256;        // 0..1023 float4 slots
        const int r = it >> 4;
        const int c = (it & 15) << 2;
        float4 bv = *(const float4*)(bp + (it << 2));
        float* s = sp + r * P_STRIDE + c;
        *(float2*)(s)     = make_float2(bv.x, bv.y);
        *(float2*)(s + 2) = make_float2(bv.z, bv.w);
    }
    __syncthreads();

    // ---- QK^T : thread (ty,tx) owns rows {ty+16i}, cols {tx+16j} --------
    const int tx = tid & 15;
    const int ty = tid >> 4;

    unsigned long long acc[4][4];
#pragma unroll
    for (int i = 0; i < 4; i++)
#pragma unroll
        for (int j = 0; j < 4; j++) acc[i][j] = 0ull;

#pragma unroll 4
    for (int dd = 0; dd < 16; dd++) {
        const int d = dd << 1;
        unsigned long long qv[4], kv[4];
#pragma unroll
        for (int i = 0; i < 4; i++)
            qv[i] = *(const unsigned long long*)(sq + (ty + 16 * i) * QK_STRIDE + d);
#pragma unroll
        for (int j = 0; j < 4; j++)
            kv[j] = *(const unsigned long long*)(sk + (tx + 16 * j) * QK_STRIDE + d);
#pragma unroll
        for (int i = 0; i < 4; i++)
#pragma unroll
            for (int j = 0; j < 4; j++)
                acc[i][j] = fma2(qv[i], kv[j], acc[i][j]);
    }

    // ---- softmax (row reductions across the 16 tx lanes) ----------------
    float val[4][4];
    float rmax[4], rsum[4];
#pragma unroll
    for (int i = 0; i < 4; i++) {
#pragma unroll
        for (int j = 0; j < 4; j++) {
            float2 p = unpack2(acc[i][j]);
            val[i][j] = (p.x + p.y) * ATT_SCALE +
                        sp[(ty + 16 * i) * P_STRIDE + tx + 16 * j];
        }
        rmax[i] = fmaxf(fmaxf(val[i][0], val[i][1]), fmaxf(val[i][2], val[i][3]));
    }
#pragma unroll
    for (int m = 8; m >= 1; m >>= 1)
#pragma unroll
        for (int i = 0; i < 4; i++)
            rmax[i] = fmaxf(rmax[i], __shfl_xor_sync(0xffffffffu, rmax[i], m));

#pragma unroll
    for (int i = 0; i < 4; i++) {
        rsum[i] = 0.0f;
#pragma unroll
        for (int j = 0; j < 4; j++) {
            val[i][j] = __expf(val[i][j] - rmax[i]);
            rsum[i] += val[i][j];
        }
    }
#pragma unroll
    for (int m = 8; m >= 1; m >>= 1)
#pragma unroll
        for (int i = 0; i < 4; i++)
            rsum[i] += __shfl_xor_sync(0xffffffffu, rsum[i], m);

#pragma unroll
    for (int i = 0; i < 4; i++)
#pragma unroll
        for (int j = 0; j < 4; j++)
            sp[(ty + 16 * i) * P_STRIDE + tx + 16 * j] = val[i][j];

    if (tx == 0) {
#pragma unroll
        for (int i = 0; i < 4; i++) sinv[ty + 16 * i] = 1.0f / rsum[i];
    }
    __syncthreads();

    // ---- P·V : thread owns out row (tid>>2), cols [(tid&3)*8 .. +7] -----
    const int r  = tid >> 2;
    const int cg = (tid & 3) << 3;
    unsigned long long acc2[4] = {0ull, 0ull, 0ull, 0ull};
    const float* prow = sp + r * P_STRIDE;

#pragma unroll 4
    for (int m = 0; m < NWIN; m++) {
        const float a = prow[m];
        const unsigned long long ap = pack2(a, a);
        const unsigned long long* vp =
            (const unsigned long long*)(sv + m * V_STRIDE + cg);
        acc2[0] = fma2(ap, vp[0], acc2[0]);
        acc2[1] = fma2(ap, vp[1], acc2[1]);
        acc2[2] = fma2(ap, vp[2], acc2[2]);
        acc2[3] = fma2(ap, vp[3], acc2[3]);
    }

    const float inv = sinv[r];
    float2 o0 = unpack2(acc2[0]);
    float2 o1 = unpack2(acc2[1]);
    float2 o2 = unpack2(acc2[2]);
    float2 o3 = unpack2(acc2[3]);

    float* op = out + (size_t)b * (NWIN * 192) + r * 192 + h * HD + cg;
    *(float4*)(op)     = make_float4(o0.x * inv, o0.y * inv, o1.x * inv, o1.y * inv);
    *(float4*)(op + 4) = make_float4(o2.x * inv, o2.y * inv, o3.x * inv, o3.y * inv);
}

// ---------------------------------------------------------------------------
extern "C" void kernel_launch(void* const* d_in, const int* in_sizes, int n_in,
                              void* d_out, int out_size) {
    const float* qkv = (const float*)d_in[0];
    const float* rel = (const float*)d_in[1];
    const float* w1  = (const float*)d_in[2];
    const float* b1  = (const float*)d_in[3];
    const float* w2  = (const float*)d_in[4];
    const float* b2  = (const float*)d_in[5];
    float* out = (float*)d_out;

    bias_kernel<<<16, 256>>>(rel, w1, b1, w2, b2);
    attn_kernel<<<dim3(NH, 2048), 256>>>(qkv, out);
}

// round 5
// speedup vs baseline: 1.4839x; 1.4839x over previous
#include <cuda_runtime.h>

#define NWIN 64
#define HD   32
#define NH   6
#define ATT_SCALE 0.17677669529663687f   // 32^-0.5
#define LOG2E 1.4426950408889634f
#define WARPS_PER_CTA 5
#define NTHREADS (WARPS_PER_CTA * 32)

typedef unsigned long long u64;

__device__ float g_biasT[NH * NWIN * NWIN];  // [h][m][interleaved row]

static __device__ __forceinline__ u64 fma2(u64 a, u64 b, u64 c) {
    u64 d;
    asm("fma.rn.f32x2 %0, %1, %2, %3;" : "=l"(d) : "l"(a), "l"(b), "l"(c));
    return d;
}
static __device__ __forceinline__ u64 add2(u64 a, u64 b) {
    u64 d;
    asm("add.rn.f32x2 %0, %1, %2;" : "=l"(d) : "l"(a), "l"(b));
    return d;
}
static __device__ __forceinline__ u64 pack2(float x, float y) {
    u64 d;
    asm("mov.b64 %0, {%1, %2};" : "=l"(d) : "f"(x), "f"(y));
    return d;
}
static __device__ __forceinline__ float2 unpack2(u64 u) {
    float2 r;
    asm("mov.b64 {%0, %1}, %2;" : "=f"(r.x), "=f"(r.y) : "l"(u));
    return r;
}
static __device__ __forceinline__ float ex2f(float x) {
    float y;
    asm("ex2.approx.ftz.f32 %0, %1;" : "=f"(y) : "f"(x));
    return y;
}

// ---------------------------------------------------------------------------
// Kernel 1: relative-position bias MLP  [64,64,2] -> g_biasT[h][m][ir]
//   ir interleaves rows: ir = 2*(r&31) + (r>>5), value pre-scaled by log2(e)
// ---------------------------------------------------------------------------
__global__ void __launch_bounds__(256)
bias_kernel(const float* __restrict__ rel, const float* __restrict__ w1,
            const float* __restrict__ b1, const float* __restrict__ w2,
            const float* __restrict__ b2) {
    __shared__ float s_w1a[256];
    __shared__ float s_w1b[256];
    __shared__ float s_b1[256];
    __shared__ float s_w2[256 * NH];

    const int tid = threadIdx.x;
    s_w1a[tid] = w1[tid];
    s_w1b[tid] = w1[256 + tid];
    s_b1[tid]  = b1[tid];
#pragma unroll
    for (int i = tid; i < 256 * NH; i += 256) s_w2[i] = w2[i];
    __syncthreads();

    const int idx = blockIdx.x * 256 + tid;  // r*64 + m
    const float r0 = rel[idx * 2 + 0];
    const float r1 = rel[idx * 2 + 1];

    float acc[NH];
#pragma unroll
    for (int o = 0; o < NH; o++) acc[o] = 0.0f;

#pragma unroll 4
    for (int hh = 0; hh < 256; hh++) {
        float a = fmaf(r0, s_w1a[hh], fmaf(r1, s_w1b[hh], s_b1[hh]));
        a = fmaxf(a, 0.0f);
#pragma unroll
        for (int o = 0; o < NH; o++) acc[o] = fmaf(a, s_w2[hh * NH + o], acc[o]);
    }
    const int r = idx >> 6;
    const int m = idx & 63;
    const int ir = ((r & 31) << 1) | (r >> 5);
#pragma unroll
    for (int o = 0; o < NH; o++)
        g_biasT[o * 4096 + m * 64 + ir] = (acc[o] + b2[o]) * LOG2E;
}

// ---------------------------------------------------------------------------
// Kernel 2: one WARP = one (b,h) window. Lane owns query rows {lane, lane+32}.
//   k[m]/v[m] rows come from per-warp smem via uniform-address broadcast LDS.
//   Streaming softmax (no max subtraction; fp32 range is ample).
// ---------------------------------------------------------------------------
__global__ void __launch_bounds__(NTHREADS, 2)
attn_kernel(const float* __restrict__ qkv, float* __restrict__ out) {
    extern __shared__ float smem[];
    float* sbias = smem;  // 4096 floats, shared by all warps (same h)

    const int tid  = threadIdx.x;
    const int lane = tid & 31;
    const int w    = tid >> 5;
    const int h    = blockIdx.x;
    const int b    = blockIdx.y * WARPS_PER_CTA + w;
    const bool active = (b < 2048);

    float* sk = smem + 4096 + w * 4096;  // 64 x 32
    float* sv = sk + 2048;               // 64 x 32

    // ---- stage bias tile (all threads participate) ----------------------
    {
        const float4* gb = (const float4*)(g_biasT + h * 4096);
#pragma unroll
        for (int i = tid; i < 1024; i += NTHREADS)
            ((float4*)sbias)[i] = gb[i];
    }

    // ---- stage k, v into per-warp smem + q rows into registers ----------
    ulonglong2 q0[8], q1[8];
    if (active) {
        const float* base = qkv + (size_t)b * (NWIN * 576) + h * HD;
        const int r4 = lane >> 3;  // 0..3
        const int f  = lane & 7;   // 0..7
#pragma unroll
        for (int i = 0; i < 16; i++) {
            const int n = i * 4 + r4;
            const float* g = base + n * 576 + f * 4;
            float4 kx = *(const float4*)(g + 192);
            float4 vx = *(const float4*)(g + 384);
            *(float4*)(sk + n * 32 + f * 4) = kx;
            *(float4*)(sv + n * 32 + f * 4) = vx;
        }
        const float* qr0 = base + lane * 576;
        const float* qr1 = base + (lane + 32) * 576;
#pragma unroll
        for (int i = 0; i < 8; i++) {
            q0[i] = *(const ulonglong2*)(qr0 + i * 4);
            q1[i] = *(const ulonglong2*)(qr1 + i * 4);
        }
    }
    __syncthreads();
    if (!active) return;

    // ---- streaming attention over key index m ---------------------------
    u64 o0[16], o1[16];
#pragma unroll
    for (int j = 0; j < 16; j++) { o0[j] = 0ull; o1[j] = 0ull; }
    u64 sums = 0ull;  // (sum row0, sum row1)

    const float* bias_l = sbias + 2 * lane;

#pragma unroll 2
    for (int m = 0; m < NWIN; m++) {
        const ulonglong2* krow = (const ulonglong2*)(sk + m * 32);
        const ulonglong2* vrow = (const ulonglong2*)(sv + m * 32);

        // dot products (packed over d): 4 chains of depth 8
        u64 d0a = 0ull, d0b = 0ull, d1a = 0ull, d1b = 0ull;
#pragma unroll
        for (int j = 0; j < 8; j += 2) {
            ulonglong2 ka = krow[j];
            ulonglong2 kb = krow[j + 1];
            d0a = fma2(q0[j].x, ka.x, d0a);
            d0b = fma2(q0[j].y, ka.y, d0b);
            d1a = fma2(q1[j].x, ka.x, d1a);
            d1b = fma2(q1[j].y, ka.y, d1b);
            d0a = fma2(q0[j + 1].x, kb.x, d0a);
            d0b = fma2(q0[j + 1].y, kb.y, d0b);
            d1a = fma2(q1[j + 1].x, kb.x, d1a);
            d1b = fma2(q1[j + 1].y, kb.y, d1b);
        }
        float2 bf = unpack2(*(const u64*)(bias_l + m * 64));  // log2e-scaled bias
        float2 p0 = unpack2(add2(d0a, d0b));
        float2 p1 = unpack2(add2(d1a, d1b));
        float e0 = ex2f(fmaf(p0.x + p0.y, ATT_SCALE * LOG2E, bf.x));
        float e1 = ex2f(fmaf(p1.x + p1.y, ATT_SCALE * LOG2E, bf.y));
        sums = add2(sums, pack2(e0, e1));
        const u64 e0p = pack2(e0, e0);
        const u64 e1p = pack2(e1, e1);

#pragma unroll
        for (int j = 0; j < 8; j++) {
            ulonglong2 vx = vrow[j];
            o0[2 * j]     = fma2(e0p, vx.x, o0[2 * j]);
            o0[2 * j + 1] = fma2(e0p, vx.y, o0[2 * j + 1]);
            o1[2 * j]     = fma2(e1p, vx.x, o1[2 * j]);
            o1[2 * j + 1] = fma2(e1p, vx.y, o1[2 * j + 1]);
        }
    }

    // ---- epilogue: normalize + store ------------------------------------
    float2 s = unpack2(sums);
    const float inv0 = 1.0f / s.x;
    const float inv1 = 1.0f / s.y;

    float* orow0 = out + (size_t)b * (NWIN * 192) + lane * 192 + h * HD;
    float* orow1 = orow0 + 32 * 192;
#pragma unroll
    for (int j = 0; j < 8; j++) {
        float2 a0 = unpack2(o0[2 * j]);
        float2 a1 = unpack2(o0[2 * j + 1]);
        *(float4*)(orow0 + 4 * j) =
            make_float4(a0.x * inv0, a0.y * inv0, a1.x * inv0, a1.y * inv0);
        float2 c0 = unpack2(o1[2 * j]);
        float2 c1 = unpack2(o1[2 * j + 1]);
        *(float4*)(orow1 + 4 * j) =
            make_float4(c0.x * inv1, c0.y * inv1, c1.x * inv1, c1.y * inv1);
    }
}

// ---------------------------------------------------------------------------
extern "C" void kernel_launch(void* const* d_in, const int* in_sizes, int n_in,
                              void* d_out, int out_size) {
    const float* qkv = (const float*)d_in[0];
    const float* rel = (const float*)d_in[1];
    const float* w1  = (const float*)d_in[2];
    const float* b1  = (const float*)d_in[3];
    const float* w2  = (const float*)d_in[4];
    const float* b2  = (const float*)d_in[5];
    float* out = (float*)d_out;

    const int smem_bytes = (4096 + WARPS_PER_CTA * 4096) * sizeof(float);  // 96 KB
    cudaFuncSetAttribute(attn_kernel, cudaFuncAttributeMaxDynamicSharedMemorySize,
                         smem_bytes);

    bias_kernel<<<16, 256>>>(rel, w1, b1, w2, b2);
    const int gy = (2048 + WARPS_PER_CTA - 1) / WARPS_PER_CTA;  // 410
    attn_kernel<<<dim3(NH, gy), NTHREADS, smem_bytes>>>(qkv, out);
}